// round 1
// baseline (speedup 1.0000x reference)
#include <cuda_runtime.h>

#define NROWTOT 32768
#define ROWS 64
#define NCTA (NROWTOT / ROWS)   // 512
#define THREADS 512
#define KC 64                    // phase A K-chunk
#define STRX 68                  // padded X row stride (floats)
#define STRW 26                  // padded W row stride (floats)
#define DC 128                   // phase C d-chunk
#define DIMD 2048
#define NC 12
#define NCC 24
#define NC2 144
#define EPSV 1e-5f

// Shared memory layout (floats):
//   sCt : [144][64]  coefficients, offset 0                       (9216)
//   sWi : [144][128] Wi tile,      offset 9216                    (18432)
//   Phase A aliases the sWi region:
//     sX : [64][STRX]  at sWi+0        (4352)
//     sW : [KC][STRW]  at sWi+4352     (1664)
//     sPV: [64][24]    at sWi+6016     (1536)   (dead before first sWi load)
#define OFF_CT   0
#define OFF_WI   (NC2 * ROWS)            // 9216
#define OFF_X    OFF_WI
#define OFF_W    (OFF_WI + ROWS * STRX)  // 9216+4352
#define OFF_PV   (OFF_W + KC * STRW)     // +1664
#define SMEM_FLOATS (OFF_WI + NC2 * DC)  // 27648
#define SMEM_BYTES (SMEM_FLOATS * 4)     // 110592

// ---- packed f32x2 helpers (sm_103a FFMA2) ----
__device__ __forceinline__ unsigned long long pack2(float x, float y) {
    unsigned long long u;
    asm("mov.b64 %0, {%1,%2};" : "=l"(u) : "f"(x), "f"(y));
    return u;
}
__device__ __forceinline__ void unpack2(unsigned long long u, float& x, float& y) {
    asm("mov.b64 {%0,%1}, %2;" : "=f"(x), "=f"(y) : "l"(u));
}
__device__ __forceinline__ unsigned long long ffma2(unsigned long long a,
                                                    unsigned long long b,
                                                    unsigned long long c) {
    unsigned long long d;
    asm("fma.rn.f32x2 %0, %1, %2, %3;" : "=l"(d) : "l"(a), "l"(b), "l"(c));
    return d;
}
__device__ __forceinline__ unsigned long long fadd2(unsigned long long a,
                                                    unsigned long long b) {
    unsigned long long d;
    asm("add.rn.f32x2 %0, %1, %2;" : "=l"(d) : "l"(a), "l"(b));
    return d;
}

__global__ __launch_bounds__(THREADS, 1)
void gil_kernel(const float* __restrict__ x, const float* __restrict__ Wp,
                const float* __restrict__ bp, const float* __restrict__ Wv,
                const float* __restrict__ bv, const float* __restrict__ Wi,
                const float* __restrict__ bi, const float* __restrict__ gamma,
                const float* __restrict__ beta, float* __restrict__ out) {
    extern __shared__ float sm[];
    float* sCt = sm + OFF_CT;
    float* sWi = sm + OFF_WI;
    float* sX  = sm + OFF_X;
    float* sW  = sm + OFF_W;
    float* sPV = sm + OFF_PV;

    const int tid = threadIdx.x;
    const int rowbase = blockIdx.x * ROWS;

    // ================= Phase A: pos/vel = x @ [Wp|Wv] + [bp|bv] =============
    // thread (rp = tid>>4, s = tid&15): rows 2rp, 2rp+1 ; k = s + 16*k4
    const int rp = tid >> 4;
    const int s  = tid & 15;
    unsigned long long a0[NC], a1[NC];
#pragma unroll
    for (int i = 0; i < NC; i++) { a0[i] = 0ull; a1[i] = 0ull; }

    for (int kc = 0; kc < DIMD / KC; kc++) {
        if (kc) __syncthreads();
        // cooperative load X chunk [64 rows x 64 k] (2 float4 per thread)
#pragma unroll
        for (int j = 0; j < 2; j++) {
            int i4 = tid * 2 + j;
            int r  = i4 >> 4;
            int kq = i4 & 15;
            float4 v = *(const float4*)(x + (rowbase + r) * DIMD + kc * KC + kq * 4);
            *(float4*)(sX + r * STRX + kq * 4) = v;
        }
        // cooperative load combined W chunk [64 k x 24 c]
#pragma unroll
        for (int j = 0; j < 3; j++) {
            int i = tid + THREADS * j;  // < 1536
            int k = i / NCC;
            int c = i - k * NCC;
            float wv = (c < NC) ? Wp[(kc * KC + k) * NC + c]
                                : Wv[(kc * KC + k) * NC + (c - NC)];
            sW[k * STRW + c] = wv;
        }
        __syncthreads();
#pragma unroll
        for (int k4 = 0; k4 < 4; k4++) {
            int k = s + 16 * k4;
            float xv0 = sX[(2 * rp) * STRX + k];
            float xv1 = sX[(2 * rp + 1) * STRX + k];
            unsigned long long x0u = pack2(xv0, xv0);
            unsigned long long x1u = pack2(xv1, xv1);
            const float* wr = sW + k * STRW;
#pragma unroll
            for (int cp = 0; cp < NC; cp++) {
                unsigned long long w2 = *(const unsigned long long*)(wr + 2 * cp);
                a0[cp] = ffma2(x0u, w2, a0[cp]);
                a1[cp] = ffma2(x1u, w2, a1[cp]);
            }
        }
    }
    // reduce across the 16 k-slices (lanes 0-15 / 16-31 hold distinct rows)
#pragma unroll
    for (int off = 8; off >= 1; off >>= 1) {
#pragma unroll
        for (int cp = 0; cp < NC; cp++) {
            a0[cp] = fadd2(a0[cp], __shfl_xor_sync(0xffffffffu, a0[cp], off));
            a1[cp] = fadd2(a1[cp], __shfl_xor_sync(0xffffffffu, a1[cp], off));
        }
    }
    if (s == 0) {
        int r0 = 2 * rp, r1 = 2 * rp + 1;
#pragma unroll
        for (int cp = 0; cp < NC; cp++) {
            float v00, v01, v10, v11;
            unpack2(a0[cp], v00, v01);
            unpack2(a1[cp], v10, v11);
            int c0 = 2 * cp, c1 = 2 * cp + 1;
            float b0 = (c0 < NC) ? bp[c0] : bv[c0 - NC];
            float b1 = (c1 < NC) ? bp[c1] : bv[c1 - NC];
            sPV[r0 * NCC + c0] = v00 + b0;
            sPV[r0 * NCC + c1] = v01 + b1;
            sPV[r1 * NCC + c0] = v10 + b0;
            sPV[r1 * NCC + c1] = v11 + b1;
        }
    }
    __syncthreads();

    // ================= Phase B: Ct[ij][r] = pos[r][i] * vel[r][j] ============
#pragma unroll
    for (int t = tid; t < NC2 * ROWS; t += THREADS) {
        int ij = t >> 6;
        int r  = t & 63;
        int i  = ij / NC;
        int j  = ij - i * NC;
        sCt[t] = sPV[r * NCC + i] * sPV[r * NCC + NC + j];
    }

    // ================= Phase C: inter = C @ Wi, + bi + x, LN stats ==========
    const int w = tid >> 5;   // warp 0..15 -> rows 4w..4w+3
    const int l = tid & 31;   // lane -> d = dbase + 4l
    float rsum[4] = {0.f, 0.f, 0.f, 0.f};
    float rssq[4] = {0.f, 0.f, 0.f, 0.f};

    for (int ch = 0; ch < DIMD / DC; ch++) {
        __syncthreads();  // protect sWi reuse (and order phase B before compute)
        int dbase = ch * DC;
#pragma unroll
        for (int j = 0; j < 9; j++) {
            int i4  = tid + THREADS * j;  // < 4608
            int ij  = i4 >> 5;
            int dd4 = i4 & 31;
            float4 v = *(const float4*)(Wi + ij * DIMD + dbase + dd4 * 4);
            *(float4*)(sWi + ij * DC + dd4 * 4) = v;
        }
        __syncthreads();

        unsigned long long acc[8];
#pragma unroll
        for (int i = 0; i < 8; i++) acc[i] = 0ull;
        const float* ctb = sCt + 4 * w;
        const float* wib = sWi + 4 * l;
#pragma unroll 8
        for (int ij = 0; ij < NC2; ij++) {
            float4 c4 = *(const float4*)(ctb + ij * ROWS);  // broadcast (4 rows)
            float4 w4 = *(const float4*)(wib + ij * DC);    // conflict-free (4 d)
            unsigned long long wlo = pack2(w4.x, w4.y);
            unsigned long long whi = pack2(w4.z, w4.w);
            unsigned long long cc;
            cc = pack2(c4.x, c4.x); acc[0] = ffma2(cc, wlo, acc[0]); acc[1] = ffma2(cc, whi, acc[1]);
            cc = pack2(c4.y, c4.y); acc[2] = ffma2(cc, wlo, acc[2]); acc[3] = ffma2(cc, whi, acc[3]);
            cc = pack2(c4.z, c4.z); acc[4] = ffma2(cc, wlo, acc[4]); acc[5] = ffma2(cc, whi, acc[5]);
            cc = pack2(c4.w, c4.w); acc[6] = ffma2(cc, wlo, acc[6]); acc[7] = ffma2(cc, whi, acc[7]);
        }

        // epilogue: y = inter + bi + x ; store un-normalized y ; LN partials
        float4 b4 = *(const float4*)(bi + dbase + 4 * l);
#pragma unroll
        for (int r = 0; r < 4; r++) {
            int row = rowbase + 4 * w + r;
            float4 xv = *(const float4*)(x + row * DIMD + dbase + 4 * l);
            float t0, t1, t2, t3;
            unpack2(acc[2 * r], t0, t1);
            unpack2(acc[2 * r + 1], t2, t3);
            float4 yv;
            yv.x = t0 + b4.x + xv.x;
            yv.y = t1 + b4.y + xv.y;
            yv.z = t2 + b4.z + xv.z;
            yv.w = t3 + b4.w + xv.w;
            *(float4*)(out + row * DIMD + dbase + 4 * l) = yv;
            rsum[r] += (yv.x + yv.y) + (yv.z + yv.w);
            rssq[r] += yv.x * yv.x + yv.y * yv.y + yv.z * yv.z + yv.w * yv.w;
        }
    }

    // ================= LayerNorm stats (warp-local: warp owns its 4 rows) ====
    float mu[4], rs[4];
#pragma unroll
    for (int r = 0; r < 4; r++) {
        float sm_ = rsum[r], sq_ = rssq[r];
#pragma unroll
        for (int off = 16; off >= 1; off >>= 1) {
            sm_ += __shfl_xor_sync(0xffffffffu, sm_, off);
            sq_ += __shfl_xor_sync(0xffffffffu, sq_, off);
        }
        float m   = sm_ * (1.0f / DIMD);
        float var = sq_ * (1.0f / DIMD) - m * m;
        mu[r] = m;
        rs[r] = rsqrtf(var + EPSV);
    }
    __syncthreads();  // global-memory visibility of y writes before re-read

    // ================= Phase D: normalize in place ==========================
    for (int c4 = l; c4 < DIMD / 4; c4 += 32) {
        int d = c4 * 4;
        float4 g4  = *(const float4*)(gamma + d);
        float4 be4 = *(const float4*)(beta + d);
#pragma unroll
        for (int r = 0; r < 4; r++) {
            int row = rowbase + 4 * w + r;
            float4 yv = *(const float4*)(out + row * DIMD + d);
            float4 o;
            o.x = (yv.x - mu[r]) * rs[r] * g4.x + be4.x;
            o.y = (yv.y - mu[r]) * rs[r] * g4.y + be4.y;
            o.z = (yv.z - mu[r]) * rs[r] * g4.z + be4.z;
            o.w = (yv.w - mu[r]) * rs[r] * g4.w + be4.w;
            *(float4*)(out + row * DIMD + d) = o;
        }
    }
}

extern "C" void kernel_launch(void* const* d_in, const int* in_sizes, int n_in,
                              void* d_out, int out_size) {
    const float* x     = (const float*)d_in[0];
    const float* Wp    = (const float*)d_in[1];
    const float* bp    = (const float*)d_in[2];
    const float* Wv    = (const float*)d_in[3];
    const float* bv    = (const float*)d_in[4];
    const float* Wi    = (const float*)d_in[5];
    const float* bi    = (const float*)d_in[6];
    const float* gamma = (const float*)d_in[7];
    const float* beta  = (const float*)d_in[8];
    float* out = (float*)d_out;

    cudaFuncSetAttribute(gil_kernel, cudaFuncAttributeMaxDynamicSharedMemorySize,
                         SMEM_BYTES);
    gil_kernel<<<NCTA, THREADS, SMEM_BYTES>>>(x, Wp, bp, Wv, bv, Wi, bi, gamma,
                                              beta, out);
}

// round 2
// speedup vs baseline: 1.1278x; 1.1278x over previous
#include <cuda_runtime.h>

#define ROWS 64
#define NCTA 512
#define THREADS 512
#define KC 64                    // phase A K-chunk
#define STRX 68                  // padded X row stride (floats)
#define STRW 26                  // padded W row stride (floats)
#define DC 256                   // phase C d-chunk (2 halves of 128)
#define NCHUNK 8                 // 2048 / 256
#define DIMD 2048
#define NC 12
#define NCC 24
#define NC2 144
#define EPSV 1e-5f

// Shared memory layout (floats):
//   sCt : [144][64]   coefficients    offset 0          (9216)
//   sWi : [144][256]  Wi tile         offset 9216       (36864)
//   sRed: [64][2]     LN cross-warp   offset 46080      (128)
//   Phase A aliases the sWi region (sX, sW, sPV).
#define OFF_CT   0
#define OFF_WI   (NC2 * ROWS)             // 9216
#define OFF_RED  (OFF_WI + NC2 * DC)      // 46080
#define SMEM_FLOATS (OFF_RED + 2 * ROWS)  // 46208
#define SMEM_BYTES (SMEM_FLOATS * 4)      // 184832
#define OFF_X    OFF_WI
#define OFF_W    (OFF_WI + ROWS * STRX)
#define OFF_PV   (OFF_W + KC * STRW)

// ---- packed f32x2 helpers (sm_103a FFMA2) ----
__device__ __forceinline__ unsigned long long pack2(float x, float y) {
    unsigned long long u;
    asm("mov.b64 %0, {%1,%2};" : "=l"(u) : "f"(x), "f"(y));
    return u;
}
__device__ __forceinline__ void unpack2(unsigned long long u, float& x, float& y) {
    asm("mov.b64 {%0,%1}, %2;" : "=f"(x), "=f"(y) : "l"(u));
}
__device__ __forceinline__ unsigned long long ffma2(unsigned long long a,
                                                    unsigned long long b,
                                                    unsigned long long c) {
    unsigned long long d;
    asm("fma.rn.f32x2 %0, %1, %2, %3;" : "=l"(d) : "l"(a), "l"(b), "l"(c));
    return d;
}
__device__ __forceinline__ unsigned long long fadd2(unsigned long long a,
                                                    unsigned long long b) {
    unsigned long long d;
    asm("add.rn.f32x2 %0, %1, %2;" : "=l"(d) : "l"(a), "l"(b));
    return d;
}

__global__ __launch_bounds__(THREADS, 1)
void gil_kernel(const float* __restrict__ x, const float* __restrict__ Wp,
                const float* __restrict__ bp, const float* __restrict__ Wv,
                const float* __restrict__ bv, const float* __restrict__ Wi,
                const float* __restrict__ bi, const float* __restrict__ gamma,
                const float* __restrict__ beta, float* __restrict__ out) {
    extern __shared__ float sm[];
    float* sCt  = sm + OFF_CT;
    float* sWi  = sm + OFF_WI;
    float* sRed = sm + OFF_RED;
    float* sX   = sm + OFF_X;
    float* sW   = sm + OFF_W;
    float* sPV  = sm + OFF_PV;

    const int tid = threadIdx.x;
    const int rowbase = blockIdx.x * ROWS;

    // ================= Phase A: pos/vel = x @ [Wp|Wv] + [bp|bv] =============
    const int rp = tid >> 4;
    const int s  = tid & 15;
    unsigned long long a0[NC], a1[NC];
#pragma unroll
    for (int i = 0; i < NC; i++) { a0[i] = 0ull; a1[i] = 0ull; }

    for (int kc = 0; kc < DIMD / KC; kc++) {
        if (kc) __syncthreads();
#pragma unroll
        for (int j = 0; j < 2; j++) {
            int i4 = tid * 2 + j;
            int r  = i4 >> 4;
            int kq = i4 & 15;
            float4 v = *(const float4*)(x + (rowbase + r) * DIMD + kc * KC + kq * 4);
            *(float4*)(sX + r * STRX + kq * 4) = v;
        }
#pragma unroll
        for (int j = 0; j < 3; j++) {
            int i = tid + THREADS * j;  // < 1536
            int k = i / NCC;
            int c = i - k * NCC;
            float wv = (c < NC) ? Wp[(kc * KC + k) * NC + c]
                                : Wv[(kc * KC + k) * NC + (c - NC)];
            sW[k * STRW + c] = wv;
        }
        __syncthreads();
#pragma unroll
        for (int k4 = 0; k4 < 4; k4++) {
            int k = s + 16 * k4;
            float xv0 = sX[(2 * rp) * STRX + k];
            float xv1 = sX[(2 * rp + 1) * STRX + k];
            unsigned long long x0u = pack2(xv0, xv0);
            unsigned long long x1u = pack2(xv1, xv1);
            const float* wr = sW + k * STRW;
#pragma unroll
            for (int cp = 0; cp < NC; cp++) {
                unsigned long long w2 = *(const unsigned long long*)(wr + 2 * cp);
                a0[cp] = ffma2(x0u, w2, a0[cp]);
                a1[cp] = ffma2(x1u, w2, a1[cp]);
            }
        }
    }
#pragma unroll
    for (int off = 8; off >= 1; off >>= 1) {
#pragma unroll
        for (int cp = 0; cp < NC; cp++) {
            a0[cp] = fadd2(a0[cp], __shfl_xor_sync(0xffffffffu, a0[cp], off));
            a1[cp] = fadd2(a1[cp], __shfl_xor_sync(0xffffffffu, a1[cp], off));
        }
    }
    if (s == 0) {
        int r0 = 2 * rp, r1 = 2 * rp + 1;
#pragma unroll
        for (int cp = 0; cp < NC; cp++) {
            float v00, v01, v10, v11;
            unpack2(a0[cp], v00, v01);
            unpack2(a1[cp], v10, v11);
            int c0 = 2 * cp, c1 = 2 * cp + 1;
            float b0 = (c0 < NC) ? bp[c0] : bv[c0 - NC];
            float b1 = (c1 < NC) ? bp[c1] : bv[c1 - NC];
            sPV[r0 * NCC + c0] = v00 + b0;
            sPV[r0 * NCC + c1] = v01 + b1;
            sPV[r1 * NCC + c0] = v10 + b0;
            sPV[r1 * NCC + c1] = v11 + b1;
        }
    }
    __syncthreads();

    // ================= Phase B: Ct[ij][r] = pos[r][i] * vel[r][j] ============
#pragma unroll
    for (int t = tid; t < NC2 * ROWS; t += THREADS) {
        int ij = t >> 6;
        int r  = t & 63;
        int i  = ij / NC;
        int j  = ij - i * NC;
        sCt[t] = sPV[r * NCC + i] * sPV[r * NCC + NC + j];
    }

    // ================= Phase C: inter = C @ Wi, + bi + x, LN partials ========
    // warp w: rows (w&7)*8 .. +7 ; d-half (w>>3)*128 ; lane l -> 4 d values
    const int w   = tid >> 5;
    const int l   = tid & 31;
    const int wr8 = (w & 7) * 8;
    const int dh  = (w >> 3) * 128;
    float rsum[8], rssq[8];
#pragma unroll
    for (int r = 0; r < 8; r++) { rsum[r] = 0.f; rssq[r] = 0.f; }

    for (int ch = 0; ch < NCHUNK; ch++) {
        __syncthreads();  // protect sWi reuse (and order phase B before compute)
        int dbase = ch * DC;
#pragma unroll
        for (int j = 0; j < 18; j++) {
            int i4 = tid + THREADS * j;  // < 9216
            int ij = i4 >> 6;
            int d4 = i4 & 63;
            float4 v = *(const float4*)(Wi + ij * DIMD + dbase + d4 * 4);
            *(float4*)(sWi + ij * DC + d4 * 4) = v;
        }
        __syncthreads();

        unsigned long long acc[16];
#pragma unroll
        for (int i = 0; i < 16; i++) acc[i] = 0ull;
        const float* ctb = sCt + wr8;
        const float* wib = sWi + dh + 4 * l;
#pragma unroll 8
        for (int ij = 0; ij < NC2; ij++) {
            float4 ca = *(const float4*)(ctb + ij * ROWS);      // rows 0-3 (bcast)
            float4 cb = *(const float4*)(ctb + ij * ROWS + 4);  // rows 4-7 (bcast)
            float4 w4 = *(const float4*)(wib + ij * DC);        // 4 d (conflict-free)
            unsigned long long wlo = pack2(w4.x, w4.y);
            unsigned long long whi = pack2(w4.z, w4.w);
            unsigned long long cc;
            cc = pack2(ca.x, ca.x); acc[0]  = ffma2(cc, wlo, acc[0]);  acc[1]  = ffma2(cc, whi, acc[1]);
            cc = pack2(ca.y, ca.y); acc[2]  = ffma2(cc, wlo, acc[2]);  acc[3]  = ffma2(cc, whi, acc[3]);
            cc = pack2(ca.z, ca.z); acc[4]  = ffma2(cc, wlo, acc[4]);  acc[5]  = ffma2(cc, whi, acc[5]);
            cc = pack2(ca.w, ca.w); acc[6]  = ffma2(cc, wlo, acc[6]);  acc[7]  = ffma2(cc, whi, acc[7]);
            cc = pack2(cb.x, cb.x); acc[8]  = ffma2(cc, wlo, acc[8]);  acc[9]  = ffma2(cc, whi, acc[9]);
            cc = pack2(cb.y, cb.y); acc[10] = ffma2(cc, wlo, acc[10]); acc[11] = ffma2(cc, whi, acc[11]);
            cc = pack2(cb.z, cb.z); acc[12] = ffma2(cc, wlo, acc[12]); acc[13] = ffma2(cc, whi, acc[13]);
            cc = pack2(cb.w, cb.w); acc[14] = ffma2(cc, wlo, acc[14]); acc[15] = ffma2(cc, whi, acc[15]);
        }

        // epilogue: y = inter + bi + x ; store un-normalized y ; LN partials
        float4 b4 = *(const float4*)(bi + dbase + dh + 4 * l);
#pragma unroll
        for (int r = 0; r < 8; r++) {
            int row = rowbase + wr8 + r;
            float4 xv = *(const float4*)(x + row * DIMD + dbase + dh + 4 * l);
            float t0, t1, t2, t3;
            unpack2(acc[2 * r], t0, t1);
            unpack2(acc[2 * r + 1], t2, t3);
            float4 yv;
            yv.x = t0 + b4.x + xv.x;
            yv.y = t1 + b4.y + xv.y;
            yv.z = t2 + b4.z + xv.z;
            yv.w = t3 + b4.w + xv.w;
            *(float4*)(out + row * DIMD + dbase + dh + 4 * l) = yv;
            rsum[r] += (yv.x + yv.y) + (yv.z + yv.w);
            rssq[r] += yv.x * yv.x + yv.y * yv.y + yv.z * yv.z + yv.w * yv.w;
        }
    }

    // ===== LN stats: lane-reduce, then combine the two d-half warps ==========
#pragma unroll
    for (int r = 0; r < 8; r++) {
#pragma unroll
        for (int off = 16; off >= 1; off >>= 1) {
            rsum[r] += __shfl_xor_sync(0xffffffffu, rsum[r], off);
            rssq[r] += __shfl_xor_sync(0xffffffffu, rssq[r], off);
        }
    }
    __syncthreads();
    if (w < 8 && l == 0) {
#pragma unroll
        for (int r = 0; r < 8; r++) {
            sRed[2 * (wr8 + r)]     = rsum[r];
            sRed[2 * (wr8 + r) + 1] = rssq[r];
        }
    }
    __syncthreads();
    if (w >= 8 && l == 0) {
#pragma unroll
        for (int r = 0; r < 8; r++) {
            sRed[2 * (wr8 + r)]     += rsum[r];
            sRed[2 * (wr8 + r) + 1] += rssq[r];
        }
    }
    __syncthreads();

    float mu[8], rs[8];
#pragma unroll
    for (int r = 0; r < 8; r++) {
        float sm_ = sRed[2 * (wr8 + r)];
        float sq_ = sRed[2 * (wr8 + r) + 1];
        float m   = sm_ * (1.0f / DIMD);
        float var = sq_ * (1.0f / DIMD) - m * m;
        mu[r] = m;
        rs[r] = rsqrtf(var + EPSV);
    }

    // ================= Phase D: normalize (each lane re-reads what it wrote) =
    for (int ch = 0; ch < NCHUNK; ch++) {
        int d = ch * DC + dh + 4 * l;
        float4 g4  = *(const float4*)(gamma + d);
        float4 be4 = *(const float4*)(beta + d);
#pragma unroll
        for (int r = 0; r < 8; r++) {
            int row = rowbase + wr8 + r;
            float4 yv = *(const float4*)(out + row * DIMD + d);
            float4 o;
            o.x = (yv.x - mu[r]) * rs[r] * g4.x + be4.x;
            o.y = (yv.y - mu[r]) * rs[r] * g4.y + be4.y;
            o.z = (yv.z - mu[r]) * rs[r] * g4.z + be4.z;
            o.w = (yv.w - mu[r]) * rs[r] * g4.w + be4.w;
            *(float4*)(out + row * DIMD + d) = o;
        }
    }
}

extern "C" void kernel_launch(void* const* d_in, const int* in_sizes, int n_in,
                              void* d_out, int out_size) {
    const float* x     = (const float*)d_in[0];
    const float* Wp    = (const float*)d_in[1];
    const float* bp    = (const float*)d_in[2];
    const float* Wv    = (const float*)d_in[3];
    const float* bv    = (const float*)d_in[4];
    const float* Wi    = (const float*)d_in[5];
    const float* bi    = (const float*)d_in[6];
    const float* gamma = (const float*)d_in[7];
    const float* beta  = (const float*)d_in[8];
    float* out = (float*)d_out;

    cudaFuncSetAttribute(gil_kernel, cudaFuncAttributeMaxDynamicSharedMemorySize,
                         SMEM_BYTES);
    gil_kernel<<<NCTA, THREADS, SMEM_BYTES>>>(x, Wp, bp, Wv, bv, Wi, bi, gamma,
                                              beta, out);
}

// round 4
// speedup vs baseline: 1.3422x; 1.1901x over previous
#include <cuda_runtime.h>
#include <cstdint>

#define DIMD 2048
#define NC 12
#define NC2 144
#define ROWS 64
#define NCTA 512
#define THREADS 512
#define DC 128
#define NCH 16
#define STR 148
#define EPSV 1e-5f
#define STRX 68
#define STRW 26

// byte offsets in dynamic smem
#define OFF_CT 0                      // sCt [64][148] tf32 (37888 B)
#define OFF_B0 37888                  // WiT buf0 [128][148] tf32 (75776 B)
#define OFF_B1 113664                 // WiT buf1
#define OFF_LN 189440                 // [4][64][2] floats (2048 B)
#define SMEM_BYTES 191488
// phase A aliases (float offsets) inside buf1
#define FOFF_X (OFF_B1 / 4)
#define FOFF_W (FOFF_X + ROWS * STRX)
#define FOFF_PV (FOFF_W + 64 * STRW)

__device__ __align__(16) uint32_t g_WiT[DIMD * NC2];  // [n][k] tf32 bits

// ---- f32x2 helpers (phase A) ----
__device__ __forceinline__ unsigned long long pack2(float x, float y) {
    unsigned long long u;
    asm("mov.b64 %0, {%1,%2};" : "=l"(u) : "f"(x), "f"(y));
    return u;
}
__device__ __forceinline__ void unpack2(unsigned long long u, float& x, float& y) {
    asm("mov.b64 {%0,%1}, %2;" : "=f"(x), "=f"(y) : "l"(u));
}
__device__ __forceinline__ unsigned long long ffma2(unsigned long long a,
                                                    unsigned long long b,
                                                    unsigned long long c) {
    unsigned long long d;
    asm("fma.rn.f32x2 %0, %1, %2, %3;" : "=l"(d) : "l"(a), "l"(b), "l"(c));
    return d;
}
__device__ __forceinline__ unsigned long long fadd2(unsigned long long a,
                                                    unsigned long long b) {
    unsigned long long d;
    asm("add.rn.f32x2 %0, %1, %2;" : "=l"(d) : "l"(a), "l"(b));
    return d;
}
__device__ __forceinline__ uint32_t smem_u32(const void* p) {
    uint32_t a;
    asm("{ .reg .u64 t; cvta.to.shared.u64 t, %1; cvt.u32.u64 %0, t; }"
        : "=r"(a) : "l"(p));
    return a;
}
__device__ __forceinline__ uint32_t to_tf32(float x) {
    uint32_t t;
    asm("cvt.rna.tf32.f32 %0, %1;" : "=r"(t) : "f"(x));
    return t;
}
__device__ __forceinline__ void mma_tf32(float& c0, float& c1, float& c2, float& c3,
                                         uint32_t a0, uint32_t a1, uint32_t a2,
                                         uint32_t a3, uint32_t b0, uint32_t b1) {
    asm volatile(
        "mma.sync.aligned.m16n8k8.row.col.f32.tf32.tf32.f32 "
        "{%0,%1,%2,%3},{%4,%5,%6,%7},{%8,%9},{%0,%1,%2,%3};"
        : "+f"(c0), "+f"(c1), "+f"(c2), "+f"(c3)
        : "r"(a0), "r"(a1), "r"(a2), "r"(a3), "r"(b0), "r"(b1));
}

// ---- pre-kernel: Wi[k][n] fp32 -> g_WiT[n][k] tf32 ----
__global__ void wit_kernel(const float* __restrict__ Wi) {
    int idx = blockIdx.x * 256 + threadIdx.x;  // over 144*2048
    int k = idx >> 11;
    int n = idx & 2047;
    g_WiT[n * NC2 + k] = to_tf32(Wi[idx]);
}

__global__ __launch_bounds__(THREADS, 1)
void gil_kernel(const float* __restrict__ x, const float* __restrict__ Wp,
                const float* __restrict__ bp, const float* __restrict__ Wv,
                const float* __restrict__ bv, const float* __restrict__ Wi,
                const float* __restrict__ bi, const float* __restrict__ gamma,
                const float* __restrict__ beta, float* __restrict__ out) {
    extern __shared__ char smc[];
    float* smf = (float*)smc;
    const int tid = threadIdx.x;
    const int rowbase = blockIdx.x * ROWS;
    const uint32_t smem_base = smem_u32(smc);

    // -------- prologue: prefetch WiT chunk 0 into buf0 (overlaps phase A) ---
    {
        const char* src = (const char*)g_WiT;  // chunk 0 starts at byte 0
#pragma unroll
        for (int j = 0; j < 9; j++) {
            int e = (tid + THREADS * j) * 16;  // byte index within 73728
            int n = e / 576;
            int ko = e - n * 576;
            uint32_t dst = smem_base + OFF_B0 + n * 592 + ko;
            asm volatile("cp.async.ca.shared.global [%0], [%1], 16;"
                         :: "r"(dst), "l"(src + e) : "memory");
        }
        asm volatile("cp.async.commit_group;" ::: "memory");
    }

    // ================= Phase A: pos/vel = x @ [Wp|Wv] + [bp|bv] (fp32) ======
    const int rp = tid >> 4;
    const int s = tid & 15;
    unsigned long long a0r[NC], a1r[NC];
#pragma unroll
    for (int i = 0; i < NC; i++) { a0r[i] = 0ull; a1r[i] = 0ull; }

    for (int kc = 0; kc < DIMD / 64; kc++) {
        if (kc) __syncthreads();
#pragma unroll
        for (int j = 0; j < 2; j++) {
            int i4 = tid * 2 + j;
            int r = i4 >> 4, kq = i4 & 15;
            float4 v = *(const float4*)(x + (rowbase + r) * DIMD + kc * 64 + kq * 4);
            *(float4*)(smf + FOFF_X + r * STRX + kq * 4) = v;
        }
#pragma unroll
        for (int j = 0; j < 3; j++) {
            int i = tid + THREADS * j;  // < 1536
            int k = i / 24, c = i - k * 24;
            float wv = (c < NC) ? Wp[(kc * 64 + k) * NC + c]
                                : Wv[(kc * 64 + k) * NC + (c - NC)];
            smf[FOFF_W + k * STRW + c] = wv;
        }
        __syncthreads();
#pragma unroll
        for (int k4 = 0; k4 < 4; k4++) {
            int k = s + 16 * k4;
            float xv0 = smf[FOFF_X + (2 * rp) * STRX + k];
            float xv1 = smf[FOFF_X + (2 * rp + 1) * STRX + k];
            unsigned long long x0u = pack2(xv0, xv0);
            unsigned long long x1u = pack2(xv1, xv1);
            const float* wr = smf + FOFF_W + k * STRW;
#pragma unroll
            for (int cp = 0; cp < NC; cp++) {
                unsigned long long w2 = *(const unsigned long long*)(wr + 2 * cp);
                a0r[cp] = ffma2(x0u, w2, a0r[cp]);
                a1r[cp] = ffma2(x1u, w2, a1r[cp]);
            }
        }
    }
#pragma unroll
    for (int off = 8; off >= 1; off >>= 1) {
#pragma unroll
        for (int cp = 0; cp < NC; cp++) {
            a0r[cp] = fadd2(a0r[cp], __shfl_xor_sync(0xffffffffu, a0r[cp], off));
            a1r[cp] = fadd2(a1r[cp], __shfl_xor_sync(0xffffffffu, a1r[cp], off));
        }
    }
    if (s == 0) {
        int r0 = 2 * rp, r1 = 2 * rp + 1;
#pragma unroll
        for (int cp = 0; cp < NC; cp++) {
            float v00, v01, v10, v11;
            unpack2(a0r[cp], v00, v01);
            unpack2(a1r[cp], v10, v11);
            int c0 = 2 * cp, c1 = 2 * cp + 1;
            float b0 = (c0 < NC) ? bp[c0] : bv[c0 - NC];
            float b1 = (c1 < NC) ? bp[c1] : bv[c1 - NC];
            smf[FOFF_PV + r0 * 24 + c0] = v00 + b0;
            smf[FOFF_PV + r0 * 24 + c1] = v01 + b1;
            smf[FOFF_PV + r1 * 24 + c0] = v10 + b0;
            smf[FOFF_PV + r1 * 24 + c1] = v11 + b1;
        }
    }
    __syncthreads();

    // ============ Phase B: sCt[row][k] = tf32(pos_i * vel_j) ================
    for (int t = tid; t < ROWS * NC2; t += THREADS) {
        int row = t / NC2;
        int k = t - row * NC2;
        int i = k / NC, j = k - i * NC;
        float ct = smf[FOFF_PV + row * 24 + i] * smf[FOFF_PV + row * 24 + NC + j];
        ((uint32_t*)smc)[row * STR + k] = to_tf32(ct);
    }

    // ================= Phase C: chunk loop, tf32 mma.sync ===================
    const int w = tid >> 5, lane = tid & 31;
    const int gq = lane >> 2, tg = lane & 3;
    const int r16 = (w & 3) * 16;
    const int cg = w >> 2;
    const int rowA = rowbase + r16 + gq;
    const int rowB = rowA + 8;
    float lsA = 0.f, qA = 0.f, lsB = 0.f, qB = 0.f;

    const uint32_t* sCt32 = (const uint32_t*)smc;

    for (int c = 0; c < NCH; c++) {
        if (c < NCH - 1) {  // prefetch chunk c+1 into the other buffer
            int nn0 = (c + 1) * DC;
            const char* src = (const char*)g_WiT + nn0 * NC2 * 4;
            uint32_t bufoff = ((c + 1) & 1) ? OFF_B1 : OFF_B0;
#pragma unroll
            for (int j = 0; j < 9; j++) {
                int e = (tid + THREADS * j) * 16;
                int n = e / 576;
                int ko = e - n * 576;
                uint32_t dst = smem_base + bufoff + n * 592 + ko;
                asm volatile("cp.async.ca.shared.global [%0], [%1], 16;"
                             :: "r"(dst), "l"(src + e) : "memory");
            }
            asm volatile("cp.async.commit_group;" ::: "memory");
            asm volatile("cp.async.wait_group 1;" ::: "memory");
        } else {
            asm volatile("cp.async.wait_group 0;" ::: "memory");
        }
        __syncthreads();  // chunk c tile + (c==0) phase B sCt visible to all

        const uint32_t* B = (const uint32_t*)(smc + ((c & 1) ? OFF_B1 : OFF_B0));
        float acc[4][4];
#pragma unroll
        for (int nt = 0; nt < 4; nt++)
#pragma unroll
            for (int q = 0; q < 4; q++) acc[nt][q] = 0.f;

        const uint32_t* Ar0 = sCt32 + (r16 + gq) * STR + tg;
        const uint32_t* Ar1 = Ar0 + 8 * STR;
        const uint32_t* Bb = B + (cg * 32 + gq) * STR + tg;
#pragma unroll
        for (int k8 = 0; k8 < 18; k8++) {
            uint32_t fa0 = Ar0[k8 * 8];
            uint32_t fa2 = Ar0[k8 * 8 + 4];
            uint32_t fa1 = Ar1[k8 * 8];
            uint32_t fa3 = Ar1[k8 * 8 + 4];
#pragma unroll
            for (int nt = 0; nt < 4; nt++) {
                uint32_t fb0 = Bb[nt * 8 * STR + k8 * 8];
                uint32_t fb1 = Bb[nt * 8 * STR + k8 * 8 + 4];
                mma_tf32(acc[nt][0], acc[nt][1], acc[nt][2], acc[nt][3],
                         fa0, fa1, fa2, fa3, fb0, fb1);
            }
        }

        // epilogue: y = inter + x + bi ; store ; LN partials
        int cbase = c * DC + cg * 32;
#pragma unroll
        for (int nt = 0; nt < 4; nt++) {
            int col = cbase + nt * 8 + 2 * tg;
            float2 biv = *(const float2*)(bi + col);
            float2 xa = *(const float2*)(x + rowA * DIMD + col);
            float y0 = acc[nt][0] + xa.x + biv.x;
            float y1 = acc[nt][1] + xa.y + biv.y;
            *(float2*)(out + rowA * DIMD + col) = make_float2(y0, y1);
            lsA += y0 + y1;
            qA += y0 * y0 + y1 * y1;
            float2 xb = *(const float2*)(x + rowB * DIMD + col);
            float y2 = acc[nt][2] + xb.x + biv.x;
            float y3 = acc[nt][3] + xb.y + biv.y;
            *(float2*)(out + rowB * DIMD + col) = make_float2(y2, y3);
            lsB += y2 + y3;
            qB += y2 * y2 + y3 * y3;
        }
        __syncthreads();  // done reading buf[c&1] before next prefetch overwrites it
    }

    // ================= LN stats =============================================
#pragma unroll
    for (int off = 1; off <= 2; off <<= 1) {
        lsA += __shfl_xor_sync(0xffffffffu, lsA, off);
        qA += __shfl_xor_sync(0xffffffffu, qA, off);
        lsB += __shfl_xor_sync(0xffffffffu, lsB, off);
        qB += __shfl_xor_sync(0xffffffffu, qB, off);
    }
    float* sLN = (float*)(smc + OFF_LN);
    if (tg == 0) {
        int rA = r16 + gq, rB = rA + 8;
        *(float2*)(sLN + (cg * 64 + rA) * 2) = make_float2(lsA, qA);
        *(float2*)(sLN + (cg * 64 + rB) * 2) = make_float2(lsB, qB);
    }
    __syncthreads();
    float sumA = 0.f, ssqA = 0.f, sumB = 0.f, ssqB = 0.f;
#pragma unroll
    for (int g2 = 0; g2 < 4; g2++) {
        float2 va = *(const float2*)(sLN + (g2 * 64 + r16 + gq) * 2);
        float2 vb = *(const float2*)(sLN + (g2 * 64 + r16 + gq + 8) * 2);
        sumA += va.x; ssqA += va.y;
        sumB += vb.x; ssqB += vb.y;
    }
    float muA = sumA * (1.0f / DIMD);
    float rsA = rsqrtf(ssqA * (1.0f / DIMD) - muA * muA + EPSV);
    float muB = sumB * (1.0f / DIMD);
    float rsB = rsqrtf(ssqB * (1.0f / DIMD) - muB * muB + EPSV);

    // ================= Phase D: normalize own writes ========================
    for (int c = 0; c < NCH; c++) {
#pragma unroll
        for (int nt = 0; nt < 4; nt++) {
            int col = c * DC + cg * 32 + nt * 8 + 2 * tg;
            float2 g2 = *(const float2*)(gamma + col);
            float2 b2 = *(const float2*)(beta + col);
            float2 ya = *(const float2*)(out + rowA * DIMD + col);
            ya.x = (ya.x - muA) * rsA * g2.x + b2.x;
            ya.y = (ya.y - muA) * rsA * g2.y + b2.y;
            *(float2*)(out + rowA * DIMD + col) = ya;
            float2 yb = *(const float2*)(out + rowB * DIMD + col);
            yb.x = (yb.x - muB) * rsB * g2.x + b2.x;
            yb.y = (yb.y - muB) * rsB * g2.y + b2.y;
            *(float2*)(out + rowB * DIMD + col) = yb;
        }
    }
}

extern "C" void kernel_launch(void* const* d_in, const int* in_sizes, int n_in,
                              void* d_out, int out_size) {
    const float* x     = (const float*)d_in[0];
    const float* Wp    = (const float*)d_in[1];
    const float* bp    = (const float*)d_in[2];
    const float* Wv    = (const float*)d_in[3];
    const float* bv    = (const float*)d_in[4];
    const float* Wi    = (const float*)d_in[5];
    const float* bi    = (const float*)d_in[6];
    const float* gamma = (const float*)d_in[7];
    const float* beta  = (const float*)d_in[8];
    float* out = (float*)d_out;

    wit_kernel<<<(DIMD * NC2) / 256, 256>>>(Wi);
    cudaFuncSetAttribute(gil_kernel, cudaFuncAttributeMaxDynamicSharedMemorySize,
                         SMEM_BYTES);
    gil_kernel<<<NCTA, THREADS, SMEM_BYTES>>>(x, Wp, bp, Wv, bv, Wi, bi, gamma,
                                              beta, out);
}